// round 14
// baseline (speedup 1.0000x reference)
#include <cuda_runtime.h>
#include <math_constants.h>

#define NN 50000
#define EE 1600000
#define EP (EE + NN)
#define GG 64
#define IND 128
#define HIDD 64
#define SCAN_BLK 1024
#define NBLK ((NN + SCAN_BLK - 1) / SCAN_BLK)

// ---------------- device scratch (no allocations allowed) ----------------
__device__ __align__(16) float g_xl[NN * HIDD];
__device__ __align__(16) float g_xr[NN * HIDD];
__device__ __align__(16) float g_h[NN * HIDD];
__device__ int g_deg[NN];          // in-degree incl. self loop
__device__ int g_off[NN + 1];      // CSR offsets (exclusive)
__device__ int g_rank[EE];         // per-edge slot within its dst segment
__device__ __align__(8) int2 g_csr[EP];  // packed {src, attr_bits}
__device__ int g_bsum[NBLK + 1];   // scan block sums
__device__ float g_pool[GG * HIDD];
__device__ float g_pcnt[GG];

// ---------------- init ----------------
__global__ void init_kernel() {
    int i = blockIdx.x * blockDim.x + threadIdx.x;
    if (i < NN) g_deg[i] = 1;   // slot 0 = self loop
    if (i < GG * HIDD) g_pool[i] = 0.f;
    if (i < GG) g_pcnt[i] = 0.f;
}

// ---------------- CSR build ----------------
// count + record rank: atomic return value is this edge's slot within its dst segment
__global__ void count_kernel(const int* __restrict__ ei) {
    int e = blockIdx.x * blockDim.x + threadIdx.x;
    if (e >= EE) return;
    g_rank[e] = atomicAdd(&g_deg[ei[EE + e]], 1);   // in [1, indeg]; slot 0 = self loop
}

// per-block inclusive scan (Hillis-Steele) of degrees
__global__ void scan1_kernel() {
    __shared__ int s[SCAN_BLK];
    int t = threadIdx.x;
    int i = blockIdx.x * SCAN_BLK + t;
    int v = (i < NN) ? g_deg[i] : 0;
    s[t] = v;
    __syncthreads();
#pragma unroll
    for (int o = 1; o < SCAN_BLK; o <<= 1) {
        int x = (t >= o) ? s[t - o] : 0;
        __syncthreads();
        s[t] += x;
        __syncthreads();
    }
    if (i < NN) g_off[i] = s[t];
    if (t == SCAN_BLK - 1) g_bsum[blockIdx.x] = s[t];
}

// exclusive scan of NBLK block sums (parallel, one 64-thread block)
__global__ void scan2_kernel() {
    __shared__ int s[64];
    int t = threadIdx.x;
    int v = (t < NBLK) ? g_bsum[t] : 0;
    s[t] = v;
    __syncthreads();
#pragma unroll
    for (int o = 1; o < 64; o <<= 1) {
        int x = (t >= o) ? s[t - o] : 0;
        __syncthreads();
        s[t] += x;
        __syncthreads();
    }
    if (t < NBLK) g_bsum[t] = s[t] - v;  // exclusive
}

__global__ void scan3_kernel() {
    int i = blockIdx.x * SCAN_BLK + threadIdx.x;
    if (i < NN) g_off[i] = g_off[i] - g_deg[i] + g_bsum[blockIdx.x];
    if (i == 0) g_off[NN] = EP;
}

// atomic-free scatter: slot fully determined by off + rank; one packed 8B store
__global__ void scatter_kernel(const int* __restrict__ ei, const float* __restrict__ ea) {
    int e = blockIdx.x * blockDim.x + threadIdx.x;
    if (e >= EE) return;
    int d = ei[EE + e];
    g_csr[g_off[d] + g_rank[e]] = make_int2(ei[e], __float_as_int(ea[e]));
}

// self-loop attr = mean of real incoming edge attrs; warp per node
__global__ void selfloop_kernel() {
    int gtid = blockIdx.x * blockDim.x + threadIdx.x;
    int node = gtid >> 5, lane = gtid & 31;
    if (node >= NN) return;
    int beg = g_off[node], end = g_off[node + 1];
    float s = 0.f;
    for (int p = beg + 1 + lane; p < end; p += 32) s += __int_as_float(g_csr[p].y);
#pragma unroll
    for (int o = 16; o; o >>= 1) s += __shfl_xor_sync(0xffffffffu, s, o);
    if (lane == 0) {
        int cnt = end - beg - 1;
        g_csr[beg] = make_int2(node, __float_as_int(s / fmaxf((float)cnt, 1.f)));
    }
}

// ---------------- node linear transforms: xl = h@Wl+bl, xr = h@Wr+br ----------------
// blockDim = (64, 4): 4 nodes per block, thread.x = out channel
template <int K, bool FROM_H>
__global__ void linear_kernel(const float* __restrict__ x,
                              const float* __restrict__ Wl, const float* __restrict__ bl,
                              const float* __restrict__ Wr, const float* __restrict__ br) {
    __shared__ float sx[4][K];
    int node = blockIdx.x * 4 + threadIdx.y;
    int c = threadIdx.x;
    if (node < NN) {
        const float* src = FROM_H ? (g_h + node * K) : (x + node * K);
        for (int k = c; k < K; k += 64) sx[threadIdx.y][k] = src[k];
    }
    __syncthreads();
    if (node >= NN) return;
    float al = bl[c], ar = br[c];
#pragma unroll 8
    for (int k = 0; k < K; k++) {
        float xv = sx[threadIdx.y][k];
        al = fmaf(xv, Wl[k * 64 + c], al);
        ar = fmaf(xv, Wr[k * 64 + c], ar);
    }
    g_xl[node * 64 + c] = al;
    g_xr[node * 64 + c] = ar;
}

// ---------------- fused GAT aggregation: warp per node, plain softmax ----------------
// Two 16-lane halves, each processing its OWN edge per iteration (no in-loop
// cross-half dependency). Each lane holds 4 channels (float4 = LDG.128 gather).
// Logit reduce = 4 shuffle stages (xor 1,2,4,8) executed once for both halves
// simultaneously => 2 SHFLs per edge. Halves combined once after the loop.
// Tail edge masked by clamping to a valid slot and forcing pe = 0.
__global__ void gat_node_kernel(const float* __restrict__ We, const float* __restrict__ att,
                                const float* __restrict__ bias, const int* __restrict__ batch,
                                int do_pool) {
    int gtid = blockIdx.x * blockDim.x + threadIdx.x;
    int node = gtid >> 5, lane = gtid & 31;
    if (node >= NN) return;
    int half = lane >> 4, hl = lane & 15;
    int beg = g_off[node], end = g_off[node + 1];

    float4 xr4 = ((const float4*)g_xr)[node * 16 + hl];
    float4 w4 = ((const float4*)We)[hl];
    float4 at4 = ((const float4*)att)[hl];

    float den = 0.f;
    float4 acc = make_float4(0.f, 0.f, 0.f, 0.f);

#pragma unroll 2
    for (int p0 = beg; p0 < end; p0 += 2) {
        int p = p0 + half;
        bool valid = (p < end);
        int pc = valid ? p : beg;          // clamp to a written slot
        int2 c2 = __ldg(&g_csr[pc]);       // {src, attr}; two halves read p0,p0+1 (coalesced)
        int s = c2.x;
        float a = __int_as_float(c2.y);
        float4 xl = ((const float4*)g_xl)[s * 16 + hl];
        float v, sum;
        v = fmaf(a, w4.x, xl.x + xr4.x); v = fmaxf(v, 0.2f * v); sum = v * at4.x;
        v = fmaf(a, w4.y, xl.y + xr4.y); v = fmaxf(v, 0.2f * v); sum = fmaf(v, at4.y, sum);
        v = fmaf(a, w4.z, xl.z + xr4.z); v = fmaxf(v, 0.2f * v); sum = fmaf(v, at4.z, sum);
        v = fmaf(a, w4.w, xl.w + xr4.w); v = fmaxf(v, 0.2f * v); sum = fmaf(v, at4.w, sum);
        sum += __shfl_xor_sync(0xffffffffu, sum, 1);
        sum += __shfl_xor_sync(0xffffffffu, sum, 2);
        sum += __shfl_xor_sync(0xffffffffu, sum, 4);
        sum += __shfl_xor_sync(0xffffffffu, sum, 8);
        if (!valid) sum = -CUDART_INF_F;   // pe = 0 for masked tail
        float pe = __expf(sum);            // logits are O(1): no overflow risk
        acc.x = fmaf(pe, xl.x, acc.x);
        acc.y = fmaf(pe, xl.y, acc.y);
        acc.z = fmaf(pe, xl.z, acc.z);
        acc.w = fmaf(pe, xl.w, acc.w);
        den += pe;
    }

    // combine the two halves (5 shuffles total, once per node)
    den   += __shfl_xor_sync(0xffffffffu, den, 16);
    acc.x += __shfl_xor_sync(0xffffffffu, acc.x, 16);
    acc.y += __shfl_xor_sync(0xffffffffu, acc.y, 16);
    acc.z += __shfl_xor_sync(0xffffffffu, acc.z, 16);
    acc.w += __shfl_xor_sync(0xffffffffu, acc.w, 16);

    float inv = 1.f / (den + 1e-16f);
    float4 b4 = ((const float4*)bias)[hl];
    float4 o;
    o.x = acc.x * inv + b4.x; o.x = o.x > 0.f ? o.x : (__expf(o.x) - 1.f);   // ELU
    o.y = acc.y * inv + b4.y; o.y = o.y > 0.f ? o.y : (__expf(o.y) - 1.f);
    o.z = acc.z * inv + b4.z; o.z = o.z > 0.f ? o.z : (__expf(o.z) - 1.f);
    o.w = acc.w * inv + b4.w; o.w = o.w > 0.f ? o.w : (__expf(o.w) - 1.f);

    if (half == 0) {   // lanes 0..15 hold all 64 channels
        ((float4*)g_h)[node * 16 + hl] = o;
        if (do_pool) {
            int g = batch[node];
            float* pb = &g_pool[g * 64 + 4 * hl];
            atomicAdd(pb + 0, o.x);
            atomicAdd(pb + 1, o.y);
            atomicAdd(pb + 2, o.z);
            atomicAdd(pb + 3, o.w);
            if (hl == 0) atomicAdd(&g_pcnt[g], 1.f);
        }
    }
}

// ---------------- head: mean-pool divide -> fc1 -> relu -> bn -> fc3 ----------------
__global__ void head_kernel(const float* __restrict__ Wfc1, const float* __restrict__ bfc1,
                            const float* __restrict__ gam, const float* __restrict__ bet,
                            const float* __restrict__ mean, const float* __restrict__ var,
                            const float* __restrict__ Wfc3, const float* __restrict__ bfc3,
                            float* __restrict__ out) {
    int g = threadIdx.x;
    if (g >= GG) return;
    float inv_cnt = 1.0f / fmaxf(g_pcnt[g], 1.0f);
    float pooled[64];
#pragma unroll
    for (int c = 0; c < 64; c++) pooled[c] = g_pool[g * 64 + c] * inv_cnt;
    float acc = bfc3[0];
    for (int j = 0; j < 32; j++) {
        float z = bfc1[j];
#pragma unroll
        for (int c = 0; c < 64; c++) z = fmaf(pooled[c], Wfc1[c * 32 + j], z);
        z = fmaxf(z, 0.f);
        z = (z - mean[j]) * rsqrtf(var[j] + 1e-5f) * gam[j] + bet[j];
        acc = fmaf(z, Wfc3[j], acc);
    }
    out[g] = acc;
}

// ---------------- launch ----------------
extern "C" void kernel_launch(void* const* d_in, const int* in_sizes, int n_in,
                              void* d_out, int out_size) {
    const float* x = (const float*)d_in[0];
    const int* ei = (const int*)d_in[1];
    const float* ea = (const float*)d_in[2];
    const int* batch = (const int*)d_in[3];
    const float* Wl1 = (const float*)d_in[4];
    const float* bl1 = (const float*)d_in[5];
    const float* Wr1 = (const float*)d_in[6];
    const float* br1 = (const float*)d_in[7];
    const float* We1 = (const float*)d_in[8];
    const float* att1 = (const float*)d_in[9];
    const float* bias1 = (const float*)d_in[10];
    const float* Wl2 = (const float*)d_in[11];
    const float* bl2 = (const float*)d_in[12];
    const float* Wr2 = (const float*)d_in[13];
    const float* br2 = (const float*)d_in[14];
    const float* We2 = (const float*)d_in[15];
    const float* att2 = (const float*)d_in[16];
    const float* bias2 = (const float*)d_in[17];
    const float* Wfc1 = (const float*)d_in[18];
    const float* bfc1 = (const float*)d_in[19];
    const float* bng = (const float*)d_in[20];
    const float* bnb = (const float*)d_in[21];
    const float* bnm = (const float*)d_in[22];
    const float* bnv = (const float*)d_in[23];
    const float* Wfc3 = (const float*)d_in[24];
    const float* bfc3 = (const float*)d_in[25];
    float* out = (float*)d_out;

    const int node_warp_grid = (NN * 32 + 255) / 256;

    // ---- CSR build (dst-sorted, atomic-free scatter) ----
    init_kernel<<<(NN + 255) / 256, 256>>>();
    count_kernel<<<(EE + 255) / 256, 256>>>(ei);
    scan1_kernel<<<NBLK, SCAN_BLK>>>();
    scan2_kernel<<<1, 64>>>();
    scan3_kernel<<<NBLK, SCAN_BLK>>>();
    scatter_kernel<<<(EE + 255) / 256, 256>>>(ei, ea);
    selfloop_kernel<<<node_warp_grid, 256>>>();

    // ---- GATv2 layer 1 ----
    linear_kernel<128, false><<<(NN + 3) / 4, dim3(64, 4)>>>(x, Wl1, bl1, Wr1, br1);
    gat_node_kernel<<<node_warp_grid, 256>>>(We1, att1, bias1, batch, 0);

    // ---- GATv2 layer 2 ----
    linear_kernel<64, true><<<(NN + 3) / 4, dim3(64, 4)>>>(nullptr, Wl2, bl2, Wr2, br2);
    gat_node_kernel<<<node_warp_grid, 256>>>(We2, att2, bias2, batch, 1);

    // ---- head ----
    head_kernel<<<1, 64>>>(Wfc1, bfc1, bng, bnb, bnm, bnv, Wfc3, bfc3, out);
}

// round 16
// speedup vs baseline: 1.1000x; 1.1000x over previous
#include <cuda_runtime.h>
#include <math_constants.h>

#define NN 50000
#define EE 1600000
#define EP (EE + NN)
#define GG 64
#define IND 128
#define HIDD 64
#define SCAN_BLK 1024
#define NBLK ((NN + SCAN_BLK - 1) / SCAN_BLK)

// ---------------- device scratch (no allocations allowed) ----------------
__device__ __align__(16) float g_xl[NN * HIDD];
__device__ __align__(16) float g_xr[NN * HIDD];
__device__ __align__(16) float g_h[NN * HIDD];
__device__ int g_deg[NN];          // in-degree incl. self loop
__device__ int g_off[NN + 1];      // CSR offsets (exclusive)
__device__ int g_rank[EE];         // per-edge slot within its dst segment
__device__ __align__(8) int2 g_csr[EP];  // packed {src, attr_bits}
__device__ int g_bsum[NBLK + 1];   // scan block sums
__device__ float g_pool[GG * HIDD];
__device__ float g_pcnt[GG];

// ---------------- init ----------------
__global__ void init_kernel() {
    int i = blockIdx.x * blockDim.x + threadIdx.x;
    if (i < NN) g_deg[i] = 1;   // slot 0 = self loop
    if (i < GG * HIDD) g_pool[i] = 0.f;
    if (i < GG) g_pcnt[i] = 0.f;
}

// ---------------- CSR build ----------------
// count + record rank: atomic return value is this edge's slot within its dst segment
__global__ void count_kernel(const int* __restrict__ ei) {
    int e = blockIdx.x * blockDim.x + threadIdx.x;
    if (e >= EE) return;
    g_rank[e] = atomicAdd(&g_deg[ei[EE + e]], 1);   // in [1, indeg]; slot 0 = self loop
}

// per-block inclusive scan (Hillis-Steele) of degrees
__global__ void scan1_kernel() {
    __shared__ int s[SCAN_BLK];
    int t = threadIdx.x;
    int i = blockIdx.x * SCAN_BLK + t;
    int v = (i < NN) ? g_deg[i] : 0;
    s[t] = v;
    __syncthreads();
#pragma unroll
    for (int o = 1; o < SCAN_BLK; o <<= 1) {
        int x = (t >= o) ? s[t - o] : 0;
        __syncthreads();
        s[t] += x;
        __syncthreads();
    }
    if (i < NN) g_off[i] = s[t];
    if (t == SCAN_BLK - 1) g_bsum[blockIdx.x] = s[t];
}

// exclusive scan of NBLK block sums (parallel, one 64-thread block)
__global__ void scan2_kernel() {
    __shared__ int s[64];
    int t = threadIdx.x;
    int v = (t < NBLK) ? g_bsum[t] : 0;
    s[t] = v;
    __syncthreads();
#pragma unroll
    for (int o = 1; o < 64; o <<= 1) {
        int x = (t >= o) ? s[t - o] : 0;
        __syncthreads();
        s[t] += x;
        __syncthreads();
    }
    if (t < NBLK) g_bsum[t] = s[t] - v;  // exclusive
}

__global__ void scan3_kernel() {
    int i = blockIdx.x * SCAN_BLK + threadIdx.x;
    if (i < NN) g_off[i] = g_off[i] - g_deg[i] + g_bsum[blockIdx.x];
    if (i == 0) g_off[NN] = EP;
}

// atomic-free scatter: slot fully determined by off + rank; one packed 8B store
__global__ void scatter_kernel(const int* __restrict__ ei, const float* __restrict__ ea) {
    int e = blockIdx.x * blockDim.x + threadIdx.x;
    if (e >= EE) return;
    int d = ei[EE + e];
    g_csr[g_off[d] + g_rank[e]] = make_int2(ei[e], __float_as_int(ea[e]));
}

// self-loop attr = mean of real incoming edge attrs; warp per node
__global__ void selfloop_kernel() {
    int gtid = blockIdx.x * blockDim.x + threadIdx.x;
    int node = gtid >> 5, lane = gtid & 31;
    if (node >= NN) return;
    int beg = g_off[node], end = g_off[node + 1];
    float s = 0.f;
    for (int p = beg + 1 + lane; p < end; p += 32) s += __int_as_float(g_csr[p].y);
#pragma unroll
    for (int o = 16; o; o >>= 1) s += __shfl_xor_sync(0xffffffffu, s, o);
    if (lane == 0) {
        int cnt = end - beg - 1;
        g_csr[beg] = make_int2(node, __float_as_int(s / fmaxf((float)cnt, 1.f)));
    }
}

// ---------------- node linear transforms: xl = h@Wl+bl, xr = h@Wr+br ----------------
// blockDim = (64, 4): 4 nodes per block, thread.x = out channel
template <int K, bool FROM_H>
__global__ void linear_kernel(const float* __restrict__ x,
                              const float* __restrict__ Wl, const float* __restrict__ bl,
                              const float* __restrict__ Wr, const float* __restrict__ br) {
    __shared__ float sx[4][K];
    int node = blockIdx.x * 4 + threadIdx.y;
    int c = threadIdx.x;
    if (node < NN) {
        const float* src = FROM_H ? (g_h + node * K) : (x + node * K);
        for (int k = c; k < K; k += 64) sx[threadIdx.y][k] = src[k];
    }
    __syncthreads();
    if (node >= NN) return;
    float al = bl[c], ar = br[c];
#pragma unroll 8
    for (int k = 0; k < K; k++) {
        float xv = sx[threadIdx.y][k];
        al = fmaf(xv, Wl[k * 64 + c], al);
        ar = fmaf(xv, Wr[k * 64 + c], ar);
    }
    g_xl[node * 64 + c] = al;
    g_xr[node * 64 + c] = ar;
}

// ---------------- fused GAT aggregation: warp per node, plain softmax ----------------
// 32 lanes x float2 (validated layout). Explicit 2-deep software pipeline:
// csr entry prefetched TWO iterations ahead, xl gather issued ONE iteration
// ahead, so the gather's ~240-cycle L2 latency overlaps a full loop body
// instead of sitting on the serial chain.
__global__ void gat_node_kernel(const float* __restrict__ We, const float* __restrict__ att,
                                const float* __restrict__ bias, const int* __restrict__ batch,
                                int do_pool) {
    int gtid = blockIdx.x * blockDim.x + threadIdx.x;
    int node = gtid >> 5, lane = gtid & 31;
    if (node >= NN) return;
    int beg = g_off[node], end = g_off[node + 1];

    float2 xr2 = ((const float2*)g_xr)[node * 32 + lane];
    float2 w = ((const float2*)We)[lane];
    float2 at = ((const float2*)att)[lane];

    float den = 0.f;
    float accx = 0.f, accy = 0.f;

    const float2* XL = (const float2*)g_xl;

    // pipeline prologue: cA = edge p, cB = edge p+1, xlA = gather for edge p
    int2 cA = __ldg(&g_csr[beg]);
    int2 cB = (beg + 1 < end) ? __ldg(&g_csr[beg + 1]) : cA;
    float2 xlA = XL[cA.x * 32 + lane];

    for (int p = beg; p < end; p++) {
        // prefetch: csr two ahead, xl gather one ahead
        int2 cC = (p + 2 < end) ? __ldg(&g_csr[p + 2]) : cB;
        float2 xlB = XL[cB.x * 32 + lane];

        // compute edge p from cA / xlA (loaded >= 1 iteration ago)
        float a = __int_as_float(cA.y);
        float v0 = xlA.x + xr2.x + a * w.x;
        v0 = v0 > 0.f ? v0 : 0.2f * v0;
        float v1 = xlA.y + xr2.y + a * w.y;
        v1 = v1 > 0.f ? v1 : 0.2f * v1;
        float sum = v0 * at.x + v1 * at.y;
#pragma unroll
        for (int o = 16; o; o >>= 1) sum += __shfl_xor_sync(0xffffffffu, sum, o);
        float pe = __expf(sum);            // logits are O(1): no overflow risk
        accx = fmaf(pe, xlA.x, accx);
        accy = fmaf(pe, xlA.y, accy);
        den += pe;

        // rotate pipeline registers
        cA = cB; cB = cC; xlA = xlB;
    }

    float inv = 1.f / (den + 1e-16f);
    float v0 = accx * inv + bias[2 * lane];
    v0 = v0 > 0.f ? v0 : (__expf(v0) - 1.f);   // ELU
    float v1 = accy * inv + bias[2 * lane + 1];
    v1 = v1 > 0.f ? v1 : (__expf(v1) - 1.f);
    ((float2*)g_h)[node * 32 + lane] = make_float2(v0, v1);

    if (do_pool) {
        int g = batch[node];
        atomicAdd(&g_pool[g * 64 + 2 * lane], v0);
        atomicAdd(&g_pool[g * 64 + 2 * lane + 1], v1);
        if (lane == 0) atomicAdd(&g_pcnt[g], 1.f);
    }
}

// ---------------- head: mean-pool divide -> fc1 -> relu -> bn -> fc3 ----------------
__global__ void head_kernel(const float* __restrict__ Wfc1, const float* __restrict__ bfc1,
                            const float* __restrict__ gam, const float* __restrict__ bet,
                            const float* __restrict__ mean, const float* __restrict__ var,
                            const float* __restrict__ Wfc3, const float* __restrict__ bfc3,
                            float* __restrict__ out) {
    int g = threadIdx.x;
    if (g >= GG) return;
    float inv_cnt = 1.0f / fmaxf(g_pcnt[g], 1.0f);
    float pooled[64];
#pragma unroll
    for (int c = 0; c < 64; c++) pooled[c] = g_pool[g * 64 + c] * inv_cnt;
    float acc = bfc3[0];
    for (int j = 0; j < 32; j++) {
        float z = bfc1[j];
#pragma unroll
        for (int c = 0; c < 64; c++) z = fmaf(pooled[c], Wfc1[c * 32 + j], z);
        z = fmaxf(z, 0.f);
        z = (z - mean[j]) * rsqrtf(var[j] + 1e-5f) * gam[j] + bet[j];
        acc = fmaf(z, Wfc3[j], acc);
    }
    out[g] = acc;
}

// ---------------- launch ----------------
extern "C" void kernel_launch(void* const* d_in, const int* in_sizes, int n_in,
                              void* d_out, int out_size) {
    const float* x = (const float*)d_in[0];
    const int* ei = (const int*)d_in[1];
    const float* ea = (const float*)d_in[2];
    const int* batch = (const int*)d_in[3];
    const float* Wl1 = (const float*)d_in[4];
    const float* bl1 = (const float*)d_in[5];
    const float* Wr1 = (const float*)d_in[6];
    const float* br1 = (const float*)d_in[7];
    const float* We1 = (const float*)d_in[8];
    const float* att1 = (const float*)d_in[9];
    const float* bias1 = (const float*)d_in[10];
    const float* Wl2 = (const float*)d_in[11];
    const float* bl2 = (const float*)d_in[12];
    const float* Wr2 = (const float*)d_in[13];
    const float* br2 = (const float*)d_in[14];
    const float* We2 = (const float*)d_in[15];
    const float* att2 = (const float*)d_in[16];
    const float* bias2 = (const float*)d_in[17];
    const float* Wfc1 = (const float*)d_in[18];
    const float* bfc1 = (const float*)d_in[19];
    const float* bng = (const float*)d_in[20];
    const float* bnb = (const float*)d_in[21];
    const float* bnm = (const float*)d_in[22];
    const float* bnv = (const float*)d_in[23];
    const float* Wfc3 = (const float*)d_in[24];
    const float* bfc3 = (const float*)d_in[25];
    float* out = (float*)d_out;

    const int node_warp_grid = (NN * 32 + 255) / 256;

    // ---- CSR build (dst-sorted, atomic-free scatter) ----
    init_kernel<<<(NN + 255) / 256, 256>>>();
    count_kernel<<<(EE + 255) / 256, 256>>>(ei);
    scan1_kernel<<<NBLK, SCAN_BLK>>>();
    scan2_kernel<<<1, 64>>>();
    scan3_kernel<<<NBLK, SCAN_BLK>>>();
    scatter_kernel<<<(EE + 255) / 256, 256>>>(ei, ea);
    selfloop_kernel<<<node_warp_grid, 256>>>();

    // ---- GATv2 layer 1 ----
    linear_kernel<128, false><<<(NN + 3) / 4, dim3(64, 4)>>>(x, Wl1, bl1, Wr1, br1);
    gat_node_kernel<<<node_warp_grid, 256>>>(We1, att1, bias1, batch, 0);

    // ---- GATv2 layer 2 ----
    linear_kernel<64, true><<<(NN + 3) / 4, dim3(64, 4)>>>(nullptr, Wl2, bl2, Wr2, br2);
    gat_node_kernel<<<node_warp_grid, 256>>>(We2, att2, bias2, batch, 1);

    // ---- head ----
    head_kernel<<<1, 64>>>(Wfc1, bfc1, bng, bnb, bnm, bnv, Wfc3, bfc3, out);
}